// round 6
// baseline (speedup 1.0000x reference)
#include <cuda_runtime.h>
#include <cuda_bf16.h>
#include <cuda_fp8.h>
#include <cstdint>
#include <math.h>

// Problem constants
#define BB    256
#define DD    2048
#define PP    8192
#define NPP   8
#define NCAMS 8
#define BGKNN 40
#define KPOS  3

// GEMM tiling (both kernels: 128x128 tiles, 8 warps, 3 stages, 32KB/stage)
#define BM 128
#define BN 128
#define STAGE_BYTES 32768
#define GEMM_SMEM (3 * STAGE_BYTES)    // 98304

#define FP8_SCALE 64.0f
#define FP8_INV   (1.0f / 4096.0f)     // 1/(64*64)

// ---------------- workspaces (static device memory; no allocs) ----------------
__device__ __align__(16) __nv_bfloat16 g_Bm[(size_t)PP * DD];    // 32 MB bf16 memory
__device__ __align__(16) unsigned char g_B8[(size_t)PP * DD];    // 16 MB fp8 memory (x64)
__device__ __align__(16) __nv_bfloat16 g_Abf[(size_t)BB * DD];   // 1 MB  mem[pt] rows bf16
__device__ __align__(16) unsigned char g_A8[(size_t)BB * DD];    // 0.5MB features fp8 (x64)
__device__ float g_score[(size_t)BB * PP];                       // 8 MB
__device__ float g_sims [(size_t)BB * PP];                       // 8 MB
__device__ int   g_pt[BB], g_py[BB], g_camArr[BB];
__device__ float g_Loff[BB], g_Lon[BB];

// ---------------- small prep kernels ----------------
__global__ void prep_meta_kernel(const int* __restrict__ targets,
                                 const int* __restrict__ apl) {
    int i = threadIdx.x;
    if (i < BB) {
        int pt = apl[targets[i]];
        g_pt[i] = pt;
        g_py[i] = pt / NPP;
        g_camArr[i] = pt % NCAMS;
    }
}

static __device__ __forceinline__ unsigned pack_fp8x4(float a, float b, float c, float d) {
    __nv_fp8x2_storage_t lo = __nv_cvt_float2_to_fp8x2(make_float2(a, b), __NV_SATFINITE, __NV_E4M3);
    __nv_fp8x2_storage_t hi = __nv_cvt_float2_to_fp8x2(make_float2(c, d), __NV_SATFINITE, __NV_E4M3);
    return (unsigned)lo | ((unsigned)hi << 16);
}

static __device__ __forceinline__ uint2 conv8_fp8(float4 v0, float4 v1) {
    uint2 o;
    o.x = pack_fp8x4(v0.x * FP8_SCALE, v0.y * FP8_SCALE, v0.z * FP8_SCALE, v0.w * FP8_SCALE);
    o.y = pack_fp8x4(v1.x * FP8_SCALE, v1.y * FP8_SCALE, v1.z * FP8_SCALE, v1.w * FP8_SCALE);
    return o;
}

static __device__ __forceinline__ uint4 conv8_bf16(float4 v0, float4 v1) {
    union { __nv_bfloat16 h[8]; uint4 u; } tmp;
    tmp.h[0] = __float2bfloat16(v0.x); tmp.h[1] = __float2bfloat16(v0.y);
    tmp.h[2] = __float2bfloat16(v0.z); tmp.h[3] = __float2bfloat16(v0.w);
    tmp.h[4] = __float2bfloat16(v1.x); tmp.h[5] = __float2bfloat16(v1.y);
    tmp.h[6] = __float2bfloat16(v1.z); tmp.h[7] = __float2bfloat16(v1.w);
    return tmp.u;
}

// B: fp32 -> bf16 (for sims) AND fp8 x64 (for score), one pass
__global__ void convB_kernel(const float* __restrict__ gm) {
    int j = blockIdx.x * blockDim.x + threadIdx.x;   // 8-float chunk
    if (j >= PP * DD / 8) return;
    const float4* s = (const float4*)(gm) + 2 * (size_t)j;
    float4 v0 = s[0], v1 = s[1];
    ((uint4*)g_Bm)[j] = conv8_bf16(v0, v1);
    ((uint2*)g_B8)[j] = conv8_fp8(v0, v1);
}

// A: features -> fp8 (score gemm), mem[pt] -> bf16 (sims gemm)
__global__ void buildA_kernel(const float* __restrict__ feats,
                              const float* __restrict__ gm) {
    const int HALF = BB * DD / 8;   // 65536
    int j = blockIdx.x * blockDim.x + threadIdx.x;
    if (j < HALF) {
        int r = j / (DD / 8), k8 = j % (DD / 8);
        const float4* s = (const float4*)(feats + (size_t)r * DD + k8 * 8);
        ((uint2*)g_A8)[j] = conv8_fp8(s[0], s[1]);
    } else if (j < 2 * HALF) {
        int jj = j - HALF;
        int r = jj / (DD / 8), k8 = jj % (DD / 8);
        const float4* s = (const float4*)(gm + (size_t)g_pt[r] * DD + k8 * 8);
        ((uint4*)g_Abf)[jj] = conv8_bf16(s[0], s[1]);
    }
}

// ---------------- bf16 GEMM: sims[256,8192] = Abf[256,2048] * Bm^T ----------------
__global__ __launch_bounds__(256) void gemm_bf16_kernel() {
    extern __shared__ char smem[];
    const unsigned smemB = (unsigned)__cvta_generic_to_shared(smem);
    const int t = threadIdx.x;
    const int lane = t & 31, warp = t >> 5;
    const int wm = warp & 3, wn = warp >> 2;
    const int bn = blockIdx.x, bm = blockIdx.y;

    float acc[2][8][4];
#pragma unroll
    for (int i = 0; i < 2; i++)
#pragma unroll
        for (int j = 0; j < 8; j++)
#pragma unroll
            for (int k = 0; k < 4; k++) acc[i][j][k] = 0.f;

    const __nv_bfloat16* gA = g_Abf + (size_t)bm * BM * DD;
    const __nv_bfloat16* gB = g_Bm  + (size_t)bn * BN * DD;

    auto loadStage = [&](int s, int kt) {
        unsigned sA = smemB + s * STAGE_BYTES;
        unsigned sB = sA + BM * 64 * 2;
#pragma unroll
        for (int i = 0; i < 4; i++) {
            int c = t + i * 256;
            int row = c >> 3, kc = c & 7;
            unsigned dA = sA + row * 128 + ((kc ^ (row & 7)) << 4);
            const void* srcA = gA + (size_t)row * DD + kt * 64 + kc * 8;
            asm volatile("cp.async.cg.shared.global [%0], [%1], 16;\n" ::"r"(dA), "l"(srcA));
            unsigned dB = sB + row * 128 + ((kc ^ (row & 7)) << 4);
            const void* srcB = gB + (size_t)row * DD + kt * 64 + kc * 8;
            asm volatile("cp.async.cg.shared.global [%0], [%1], 16;\n" ::"r"(dB), "l"(srcB));
        }
        asm volatile("cp.async.commit_group;\n");
    };

    const int KT = DD / 64;   // 32
    for (int s = 0; s < 2; s++) loadStage(s, s);

    for (int kt = 0; kt < KT; kt++) {
        asm volatile("cp.async.wait_group 1;\n");
        __syncthreads();
        int nk = kt + 2;
        if (nk < KT) loadStage(nk % 3, nk);
        else asm volatile("cp.async.commit_group;\n");

        int s = kt % 3;
        unsigned sA = smemB + s * STAGE_BYTES;
        unsigned sB = sA + BM * 64 * 2;
#pragma unroll
        for (int ks = 0; ks < 4; ks++) {
            unsigned af[2][4];
#pragma unroll
            for (int mt = 0; mt < 2; mt++) {
                int row = wm * 32 + mt * 16 + (lane & 15);
                int cch = ks * 2 + (lane >> 4);
                unsigned ad = sA + row * 128 + ((cch ^ (row & 7)) << 4);
                asm volatile("ldmatrix.sync.aligned.m8n8.x4.shared.b16 {%0,%1,%2,%3}, [%4];\n"
                             : "=r"(af[mt][0]), "=r"(af[mt][1]), "=r"(af[mt][2]), "=r"(af[mt][3])
                             : "r"(ad));
            }
            unsigned bq[4][4];
#pragma unroll
            for (int pr = 0; pr < 4; pr++) {
                int row = wn * 64 + pr * 16 + (lane & 7) + ((lane & 16) >> 1);
                int cch = ks * 2 + ((lane >> 3) & 1);
                unsigned ad = sB + row * 128 + ((cch ^ (row & 7)) << 4);
                asm volatile("ldmatrix.sync.aligned.m8n8.x4.shared.b16 {%0,%1,%2,%3}, [%4];\n"
                             : "=r"(bq[pr][0]), "=r"(bq[pr][1]), "=r"(bq[pr][2]), "=r"(bq[pr][3])
                             : "r"(ad));
            }
#pragma unroll
            for (int mt = 0; mt < 2; mt++)
#pragma unroll
                for (int nt = 0; nt < 8; nt++) {
                    unsigned b0 = bq[nt >> 1][(nt & 1) * 2];
                    unsigned b1 = bq[nt >> 1][(nt & 1) * 2 + 1];
                    asm volatile(
                        "mma.sync.aligned.m16n8k16.row.col.f32.bf16.bf16.f32 "
                        "{%0,%1,%2,%3}, {%4,%5,%6,%7}, {%8,%9}, {%0,%1,%2,%3};\n"
                        : "+f"(acc[mt][nt][0]), "+f"(acc[mt][nt][1]),
                          "+f"(acc[mt][nt][2]), "+f"(acc[mt][nt][3])
                        : "r"(af[mt][0]), "r"(af[mt][1]), "r"(af[mt][2]), "r"(af[mt][3]),
                          "r"(b0), "r"(b1));
                }
        }
    }

    float* outBase = g_sims + (size_t)bm * BM * PP;
    int g = lane >> 2, tg = lane & 3;
#pragma unroll
    for (int mt = 0; mt < 2; mt++) {
        int m0 = wm * 32 + mt * 16 + g;
#pragma unroll
        for (int nt = 0; nt < 8; nt++) {
            int n = bn * BN + wn * 64 + nt * 8 + tg * 2;
            *(float2*)(outBase + (size_t)m0 * PP + n) =
                make_float2(acc[mt][nt][0], acc[mt][nt][1]);
            *(float2*)(outBase + (size_t)(m0 + 8) * PP + n) =
                make_float2(acc[mt][nt][2], acc[mt][nt][3]);
        }
    }
}

// ---------------- fp8 GEMM: score[256,8192] = (A8 * B8^T) / 4096 ----------------
// Same smem geometry (128B rows = 128 fp8 = one K-chunk), same swizzle/ldmatrix.
__global__ __launch_bounds__(256) void gemm_f8_kernel() {
    extern __shared__ char smem[];
    const unsigned smemB = (unsigned)__cvta_generic_to_shared(smem);
    const int t = threadIdx.x;
    const int lane = t & 31, warp = t >> 5;
    const int wm = warp & 3, wn = warp >> 2;
    const int bn = blockIdx.x, bm = blockIdx.y;

    float acc[2][8][4];
#pragma unroll
    for (int i = 0; i < 2; i++)
#pragma unroll
        for (int j = 0; j < 8; j++)
#pragma unroll
            for (int k = 0; k < 4; k++) acc[i][j][k] = 0.f;

    const unsigned char* gA = g_A8 + (size_t)bm * BM * DD;
    const unsigned char* gB = g_B8 + (size_t)bn * BN * DD;

    auto loadStage = [&](int s, int kt) {
        unsigned sA = smemB + s * STAGE_BYTES;
        unsigned sB = sA + BM * 128;
#pragma unroll
        for (int i = 0; i < 4; i++) {
            int c = t + i * 256;
            int row = c >> 3, kc = c & 7;
            unsigned dA = sA + row * 128 + ((kc ^ (row & 7)) << 4);
            const void* srcA = gA + (size_t)row * DD + kt * 128 + kc * 16;
            asm volatile("cp.async.cg.shared.global [%0], [%1], 16;\n" ::"r"(dA), "l"(srcA));
            unsigned dB = sB + row * 128 + ((kc ^ (row & 7)) << 4);
            const void* srcB = gB + (size_t)row * DD + kt * 128 + kc * 16;
            asm volatile("cp.async.cg.shared.global [%0], [%1], 16;\n" ::"r"(dB), "l"(srcB));
        }
        asm volatile("cp.async.commit_group;\n");
    };

    const int KT = DD / 128;   // 16
    for (int s = 0; s < 2; s++) loadStage(s, s);

    for (int kt = 0; kt < KT; kt++) {
        asm volatile("cp.async.wait_group 1;\n");
        __syncthreads();
        int nk = kt + 2;
        if (nk < KT) loadStage(nk % 3, nk);
        else asm volatile("cp.async.commit_group;\n");

        int s = kt % 3;
        unsigned sA = smemB + s * STAGE_BYTES;
        unsigned sB = sA + BM * 128;
#pragma unroll
        for (int ks = 0; ks < 4; ks++) {         // each ks = 32 fp8 of K
            unsigned af[2][4];
#pragma unroll
            for (int mt = 0; mt < 2; mt++) {
                int row = wm * 32 + mt * 16 + (lane & 15);
                int cch = ks * 2 + (lane >> 4);
                unsigned ad = sA + row * 128 + ((cch ^ (row & 7)) << 4);
                asm volatile("ldmatrix.sync.aligned.m8n8.x4.shared.b16 {%0,%1,%2,%3}, [%4];\n"
                             : "=r"(af[mt][0]), "=r"(af[mt][1]), "=r"(af[mt][2]), "=r"(af[mt][3])
                             : "r"(ad));
            }
            unsigned bq[4][4];
#pragma unroll
            for (int pr = 0; pr < 4; pr++) {
                int row = wn * 64 + pr * 16 + (lane & 7) + ((lane & 16) >> 1);
                int cch = ks * 2 + ((lane >> 3) & 1);
                unsigned ad = sB + row * 128 + ((cch ^ (row & 7)) << 4);
                asm volatile("ldmatrix.sync.aligned.m8n8.x4.shared.b16 {%0,%1,%2,%3}, [%4];\n"
                             : "=r"(bq[pr][0]), "=r"(bq[pr][1]), "=r"(bq[pr][2]), "=r"(bq[pr][3])
                             : "r"(ad));
            }
#pragma unroll
            for (int mt = 0; mt < 2; mt++)
#pragma unroll
                for (int nt = 0; nt < 8; nt++) {
                    unsigned b0 = bq[nt >> 1][(nt & 1) * 2];
                    unsigned b1 = bq[nt >> 1][(nt & 1) * 2 + 1];
                    asm volatile(
                        "mma.sync.aligned.m16n8k32.row.col.f32.e4m3.e4m3.f32 "
                        "{%0,%1,%2,%3}, {%4,%5,%6,%7}, {%8,%9}, {%0,%1,%2,%3};\n"
                        : "+f"(acc[mt][nt][0]), "+f"(acc[mt][nt][1]),
                          "+f"(acc[mt][nt][2]), "+f"(acc[mt][nt][3])
                        : "r"(af[mt][0]), "r"(af[mt][1]), "r"(af[mt][2]), "r"(af[mt][3]),
                          "r"(b0), "r"(b1));
                }
        }
    }

    float* outBase = g_score + (size_t)bm * BM * PP;
    int g = lane >> 2, tg = lane & 3;
#pragma unroll
    for (int mt = 0; mt < 2; mt++) {
        int m0 = wm * 32 + mt * 16 + g;
#pragma unroll
        for (int nt = 0; nt < 8; nt++) {
            int n = bn * BN + wn * 64 + nt * 8 + tg * 2;
            *(float2*)(outBase + (size_t)m0 * PP + n) =
                make_float2(acc[mt][nt][0] * FP8_INV, acc[mt][nt][1] * FP8_INV);
            *(float2*)(outBase + (size_t)(m0 + 8) * PP + n) =
                make_float2(acc[mt][nt][2] * FP8_INV, acc[mt][nt][3] * FP8_INV);
        }
    }
}

// ---------------- radix top-K helpers ----------------
__device__ __forceinline__ unsigned f2key(float v) {
    unsigned u = __float_as_uint(v);
    return (u & 0x80000000u) ? ~u : (u | 0x80000000u);
}
__device__ __forceinline__ float key2f(unsigned u) {
    unsigned b = (u & 0x80000000u) ? (u ^ 0x80000000u) : ~u;
    return __uint_as_float(b);
}
__device__ __forceinline__ void hist_add(unsigned* hist, unsigned d) {
    unsigned am = __activemask();
    unsigned mm = __match_any_sync(am, d);
    int leader = __ffs(mm) - 1;
    if ((int)(threadIdx.x & 31) == leader) atomicAdd(&hist[d], (unsigned)__popc(mm));
}
// Warp-shuffle suffix scan over 256-bin hist. Writes sh[0]=digit, sh[1]=new rem,
// sh[2]=count of elements with digit >= selected (suffix incl).
__device__ __forceinline__ void select_digit(unsigned* hist, unsigned* aux,
                                             unsigned* sh, int rem) {
    const int t = threadIdx.x, l = t & 31, w = t >> 5;
    unsigned v = hist[t];
    unsigned s = v;
#pragma unroll
    for (int off = 1; off < 32; off <<= 1) {
        unsigned o = __shfl_down_sync(0xffffffffu, s, off);
        if (l + off < 32) s += o;
    }
    if (l == 0) aux[w] = s;
    __syncthreads();
    if (t < 8) { unsigned a = 0; for (int j = t; j < 8; j++) a += aux[j]; aux[8 + t] = a; }
    __syncthreads();
    unsigned tail = (w < 7) ? aux[8 + w + 1] : 0;
    unsigned sfx_t = s + tail;
    unsigned sfx_nx = sfx_t - v;
    if (sfx_t >= (unsigned)rem && sfx_nx < (unsigned)rem) {
        sh[0] = (unsigned)t;
        sh[1] = (unsigned)rem - sfx_nx;
        sh[2] = sfx_t;
    }
    __syncthreads();
}

#define SCAP 1024

// ---------------- merged loss kernel (512 blocks: 0-255 off, 256-511 on) ----------------
__global__ __launch_bounds__(256) void loss_kernel() {
    __shared__ unsigned keys[PP];        // 32 KB
    __shared__ unsigned skey[SCAP];      // 4 KB
    __shared__ int      sidx[SCAP];      // 4 KB
    __shared__ unsigned hist[256];
    __shared__ unsigned aux[16];
    __shared__ float    fval[BGKNN + NPP];
    __shared__ int      idxl[BGKNN];
    __shared__ int      boost[KPOS];
    __shared__ unsigned ck[256];
    __shared__ int      ci[256];
    __shared__ unsigned sh[8];

    const int bx = blockIdx.x;
    const int mode = bx >> 8;            // 0 = offline, 1 = online
    const int row = bx & 255;
    const int t = threadIdx.x;

    if (mode == 0) {
        const float* src = g_score + (size_t)row * PP;
        const int p0 = g_py[row] * NPP;
        for (int p = t; p < PP; p += 256) {
            unsigned u = f2key(src[p]);
            keys[p] = ((unsigned)(p - p0) < 8u) ? 0u : u;     // mask positives
        }
        __syncthreads();
    } else {
        const float* ssrc = g_sims + (size_t)row * PP;
        unsigned bk = 0; int bi = 0x7fffffff;
        for (int p = t; p < PP; p += 256) {
            unsigned u = f2key(ssrc[p]);
            keys[p] = u;
            if (u > bk) { bk = u; bi = p >> 3; }              // cam = p & 7 == t & 7
        }
        ck[t] = bk; ci[t] = bi;
        __syncthreads();
        for (int s = 128; s >= 8; s >>= 1) {
            if (t < s) {
                unsigned ok = ck[t + s]; int oi = ci[t + s];
                if (ok > ck[t] || (ok == ck[t] && oi < ci[t])) { ck[t] = ok; ci[t] = oi; }
            }
            __syncthreads();
        }
        if (t == 0) {
            bool used[NCAMS] = {};
            for (int j = 0; j < KPOS; j++) {
                int bc = -1; unsigned bv = 0;
                for (int c = 0; c < NCAMS; c++)
                    if (!used[c] && (bc < 0 || ck[c] > bv)) { bc = c; bv = ck[c]; }
                used[bc] = true;
                int proxy = ci[bc] * NCAMS + bc;
                boost[j] = proxy;
                keys[proxy] = 0u;        // exclude from background top-40
            }
        }
        __syncthreads();
    }

    // ---- pass 1: 256-bin histogram on top byte ----
    hist[t] = 0;
    if (t == 0) sh[3] = 0;
    __syncthreads();
    for (int p = t; p < PP; p += 256) hist_add(hist, keys[p] >> 24);
    __syncthreads();
    int rem = BGKNN;
    select_digit(hist, aux, sh, rem);
    unsigned d1 = sh[0];
    rem = (int)sh[1];
    const unsigned cntGe = sh[2];
    unsigned prefix = d1 << 24;

    // ---- compact survivors (top byte >= d1) ----
    const bool useC = (cntGe <= SCAP);
    int scnt;
    if (useC) {
        for (int p = t; p < PP; p += 256) {
            unsigned u = keys[p];
            if ((u >> 24) >= d1) {
                unsigned pos = atomicAdd(&sh[3], 1u);
                skey[pos] = u; sidx[pos] = p;
            }
        }
        scnt = (int)cntGe;
    } else {
        scnt = PP;
    }
    __syncthreads();

    // ---- passes 2-4 over survivors ----
    for (int pass = 1; pass < 4; pass++) {
        const int shift = 24 - 8 * pass;
        const unsigned mask = 0xFFFFFFFFu << (shift + 8);
        hist[t] = 0;
        __syncthreads();
        for (int i = t; i < scnt; i += 256) {
            unsigned u = useC ? skey[i] : keys[i];
            if ((u & mask) == prefix) hist_add(hist, (u >> shift) & 255u);
        }
        __syncthreads();
        select_digit(hist, aux, sh, rem);
        prefix |= sh[0] << shift;
        rem = (int)sh[1];
        __syncthreads();
    }
    const unsigned T = prefix;
    const int need = rem;
    if (t == 0) { sh[4] = 0; sh[5] = 0; }
    __syncthreads();

    // ---- collect top-40 ----
    for (int i = t; i < scnt; i += 256) {
        unsigned u = useC ? skey[i] : keys[i];
        int idx = useC ? sidx[i] : i;
        if (u > T) {
            unsigned s2 = atomicAdd(&sh[5], 1u);
            if (mode == 0) fval[s2] = key2f(u); else idxl[s2] = idx;
        } else if (u == T) {
            unsigned e = atomicAdd(&sh[4], 1u);
            if (e < (unsigned)need) {
                unsigned s2 = atomicAdd(&sh[5], 1u);
                if (mode == 0) fval[s2] = key2f(u); else idxl[s2] = idx;
            }
        }
    }
    __syncthreads();

    // ---- gather values + positives ----
    if (mode == 0) {
        if (t < NPP) {
            const float* src = g_score + (size_t)row * PP;
            fval[BGKNN + t] = src[g_py[row] * NPP + t];
        }
    } else {
        const float* inp = g_score + (size_t)row * PP;   // values come from inputs!
        if (t < BGKNN) fval[t] = inp[idxl[t]];
        else if (t < BGKNN + KPOS) fval[t] = inp[boost[t - BGKNN]];
    }
    __syncthreads();

    // ---- log-sum-exp loss by warp 0 ----
    if (t < 32) {
        const int K = mode ? (BGKNN + KPOS) : (BGKNN + NPP);
        const int pcnt = mode ? KPOS : NPP;
        float a = (t < K) ? fval[t] * 10.0f : -1e30f;
        float b = (t + 32 < K) ? fval[t + 32] * 10.0f : -1e30f;
        float m = fmaxf(a, b);
#pragma unroll
        for (int o = 16; o; o >>= 1) m = fmaxf(m, __shfl_xor_sync(0xffffffffu, m, o));
        float e = 0.f, ps = 0.f;
        if (t < K) e += __expf(a - m);
        if (t + 32 < K) e += __expf(b - m);
        if (t + 32 >= BGKNN && t + 32 < BGKNN + pcnt) ps = b;
#pragma unroll
        for (int o = 16; o; o >>= 1) {
            e += __shfl_xor_sync(0xffffffffu, e, o);
            ps += __shfl_xor_sync(0xffffffffu, ps, o);
        }
        if (t == 0) {
            float L = m + logf(e) - ps / (float)pcnt;
            if (mode) g_Lon[row] = L; else g_Loff[row] = L;
        }
    }
}

// ---------------- deterministic parallel finalize ----------------
__global__ void finalize_kernel(float* out) {
    __shared__ float lo[BB], ln[BB];
    __shared__ int cm[BB];
    __shared__ float acc[NCAMS];
    int t = threadIdx.x;
    lo[t] = g_Loff[t]; ln[t] = g_Lon[t]; cm[t] = g_camArr[t];
    __syncthreads();
    if (t < NCAMS) {
        float so = 0.f, sn = 0.f; int n = 0;
        for (int i = 0; i < BB; i++)
            if (cm[i] == t) { so += lo[i]; sn += ln[i]; n++; }
        acc[t] = (n > 0) ? (so / n + sn / n) : 0.f;
    }
    __syncthreads();
    if (t == 0) {
        float L = 0.f;
        for (int c = 0; c < NCAMS; c++) L += acc[c];
        out[0] = L;
    }
}

// ---------------- launch ----------------
extern "C" void kernel_launch(void* const* d_in, const int* in_sizes, int n_in,
                              void* d_out, int out_size) {
    const float* features = (const float*)d_in[0];
    const float* gmemory  = (const float*)d_in[1];
    const int*   targets  = (const int*)d_in[2];
    const int*   apl      = (const int*)d_in[3];
    float* out = (float*)d_out;

    prep_meta_kernel<<<1, 256>>>(targets, apl);
    convB_kernel<<<PP * DD / 8 / 256, 256>>>(gmemory);
    buildA_kernel<<<2 * BB * DD / 8 / 256, 256>>>(features, gmemory);

    cudaFuncSetAttribute(gemm_f8_kernel, cudaFuncAttributeMaxDynamicSharedMemorySize, GEMM_SMEM);
    cudaFuncSetAttribute(gemm_bf16_kernel, cudaFuncAttributeMaxDynamicSharedMemorySize, GEMM_SMEM);
    gemm_f8_kernel<<<dim3(PP / BN, BB / BM), 256, GEMM_SMEM>>>();
    gemm_bf16_kernel<<<dim3(PP / BN, BB / BM), 256, GEMM_SMEM>>>();

    loss_kernel<<<2 * BB, 256>>>();
    finalize_kernel<<<1, 256>>>(out);
}

// round 8
// speedup vs baseline: 1.1833x; 1.1833x over previous
#include <cuda_runtime.h>
#include <cuda_bf16.h>
#include <cstdint>
#include <math.h>

// Problem constants
#define BB    256
#define DD    2048
#define PP    8192
#define NPP   8
#define NCAMS 8
#define BGKNN 40
#define KPOS  3
#define MTOT  512   // 256 feature rows + 256 gathered memory rows

// GEMM tiling
#define BM 128
#define BN 128
#define BKK 64
#define STAGES 3
#define STAGE_BYTES (2 * BM * BKK * 2)        // A tile + B tile, bf16: 32768
#define GEMM_SMEM (STAGES * STAGE_BYTES)      // 98304

// ---------------- workspaces (static device memory; no allocs) ----------------
__device__ __align__(16) __nv_bfloat16 g_A[(size_t)MTOT * DD];   // 2 MB
__device__ __align__(16) __nv_bfloat16 g_Bm[(size_t)PP * DD];    // 32 MB
__device__ float g_score[(size_t)BB * PP];                       // 8 MB
__device__ float g_sims [(size_t)BB * PP];                       // 8 MB
__device__ float g_Loff[BB], g_Lon[BB];

static __device__ __forceinline__ uint4 conv8_bf16(float4 v0, float4 v1) {
    union { __nv_bfloat16 h[8]; uint4 u; } tmp;
    tmp.h[0] = __float2bfloat16(v0.x); tmp.h[1] = __float2bfloat16(v0.y);
    tmp.h[2] = __float2bfloat16(v0.z); tmp.h[3] = __float2bfloat16(v0.w);
    tmp.h[4] = __float2bfloat16(v1.x); tmp.h[5] = __float2bfloat16(v1.y);
    tmp.h[6] = __float2bfloat16(v1.z); tmp.h[7] = __float2bfloat16(v1.w);
    return tmp.u;
}

// ---------------- merged conversion kernel: B -> bf16, A = [features; mem[pt]] ----------------
#define NBCHUNK (PP * DD / 8)        // 2,097,152
#define NACHUNK (MTOT * DD / 8)      // 131,072
__global__ void conv_kernel(const float* __restrict__ gm,
                            const float* __restrict__ feats,
                            const int* __restrict__ targets,
                            const int* __restrict__ apl) {
    int j = blockIdx.x * blockDim.x + threadIdx.x;
    if (j < NBCHUNK) {
        const float4* s = (const float4*)gm + 2 * (size_t)j;
        ((uint4*)g_Bm)[j] = conv8_bf16(s[0], s[1]);
    } else {
        int jj = j - NBCHUNK;
        if (jj < NACHUNK) {
            int r = jj / (DD / 8), k8 = jj % (DD / 8);
            const float* srcRow;
            if (r < BB) srcRow = feats + (size_t)r * DD;
            else        srcRow = gm + (size_t)apl[targets[r - BB]] * DD;
            const float4* s = (const float4*)(srcRow + k8 * 8);
            ((uint4*)g_A)[jj] = conv8_bf16(s[0], s[1]);
        }
    }
}

// ---------------- GEMM: C[512,8192] = A[512,2048] * B[8192,2048]^T ----------------
// launch_bounds(256,2): regs <= 128 so 2 CTAs (16 warps = 4 warps/SMSP) can co-reside.
// Carveout attribute set host-side to allow 2 x 96KB smem per SM.
__global__ __launch_bounds__(256, 2) void gemm_kernel() {
    extern __shared__ char smem[];
    const unsigned smemB = (unsigned)__cvta_generic_to_shared(smem);
    const int t = threadIdx.x;
    const int lane = t & 31, warp = t >> 5;
    const int wm = warp & 3;   // 4 m-warps (32 rows each)
    const int wn = warp >> 2;  // 2 n-warps (64 cols each)
    const int bn = blockIdx.x, bm = blockIdx.y;

    float acc[2][8][4];
#pragma unroll
    for (int i = 0; i < 2; i++)
#pragma unroll
        for (int j = 0; j < 8; j++)
#pragma unroll
            for (int k = 0; k < 4; k++) acc[i][j][k] = 0.f;

    const __nv_bfloat16* gA = g_A  + (size_t)bm * BM * DD;
    const __nv_bfloat16* gB = g_Bm + (size_t)bn * BN * DD;

    auto loadStage = [&](int s, int kt) {
        unsigned sA = smemB + s * STAGE_BYTES;
        unsigned sB = sA + BM * BKK * 2;
#pragma unroll
        for (int i = 0; i < 4; i++) {
            int c = t + i * 256;          // chunk 0..1023 (128 rows x 8 x 16B)
            int row = c >> 3, kc = c & 7;
            unsigned dA = sA + row * 128 + ((kc ^ (row & 7)) << 4);
            const void* srcA = gA + (size_t)row * DD + kt * BKK + kc * 8;
            asm volatile("cp.async.cg.shared.global [%0], [%1], 16;\n" ::"r"(dA), "l"(srcA));
            unsigned dB = sB + row * 128 + ((kc ^ (row & 7)) << 4);
            const void* srcB = gB + (size_t)row * DD + kt * BKK + kc * 8;
            asm volatile("cp.async.cg.shared.global [%0], [%1], 16;\n" ::"r"(dB), "l"(srcB));
        }
        asm volatile("cp.async.commit_group;\n");
    };

    const int KT = DD / BKK;   // 32
    for (int s = 0; s < STAGES - 1; s++) loadStage(s, s);

    for (int kt = 0; kt < KT; kt++) {
        asm volatile("cp.async.wait_group %0;\n" ::"n"(STAGES - 2));
        __syncthreads();
        int nk = kt + STAGES - 1;
        if (nk < KT) loadStage(nk % STAGES, nk);
        else asm volatile("cp.async.commit_group;\n");

        int s = kt % STAGES;
        unsigned sA = smemB + s * STAGE_BYTES;
        unsigned sB = sA + BM * BKK * 2;
#pragma unroll
        for (int ks = 0; ks < 4; ks++) {
            unsigned af[2][4];
#pragma unroll
            for (int mt = 0; mt < 2; mt++) {
                int row = wm * 32 + mt * 16 + (lane & 15);
                int cch = ks * 2 + (lane >> 4);
                unsigned ad = sA + row * 128 + ((cch ^ (row & 7)) << 4);
                asm volatile("ldmatrix.sync.aligned.m8n8.x4.shared.b16 {%0,%1,%2,%3}, [%4];\n"
                             : "=r"(af[mt][0]), "=r"(af[mt][1]), "=r"(af[mt][2]), "=r"(af[mt][3])
                             : "r"(ad));
            }
            unsigned bq[4][4];
#pragma unroll
            for (int pr = 0; pr < 4; pr++) {
                int row = wn * 64 + pr * 16 + (lane & 7) + ((lane & 16) >> 1);
                int cch = ks * 2 + ((lane >> 3) & 1);
                unsigned ad = sB + row * 128 + ((cch ^ (row & 7)) << 4);
                asm volatile("ldmatrix.sync.aligned.m8n8.x4.shared.b16 {%0,%1,%2,%3}, [%4];\n"
                             : "=r"(bq[pr][0]), "=r"(bq[pr][1]), "=r"(bq[pr][2]), "=r"(bq[pr][3])
                             : "r"(ad));
            }
#pragma unroll
            for (int mt = 0; mt < 2; mt++)
#pragma unroll
                for (int nt = 0; nt < 8; nt++) {
                    unsigned b0 = bq[nt >> 1][(nt & 1) * 2];
                    unsigned b1 = bq[nt >> 1][(nt & 1) * 2 + 1];
                    asm volatile(
                        "mma.sync.aligned.m16n8k16.row.col.f32.bf16.bf16.f32 "
                        "{%0,%1,%2,%3}, {%4,%5,%6,%7}, {%8,%9}, {%0,%1,%2,%3};\n"
                        : "+f"(acc[mt][nt][0]), "+f"(acc[mt][nt][1]),
                          "+f"(acc[mt][nt][2]), "+f"(acc[mt][nt][3])
                        : "r"(af[mt][0]), "r"(af[mt][1]), "r"(af[mt][2]), "r"(af[mt][3]),
                          "r"(b0), "r"(b1));
                }
        }
    }

    // epilogue: rows 0-255 -> g_score, rows 256-511 -> g_sims (bm is tile of 128)
    float* outBase = (bm < 2) ? (g_score + (size_t)bm * BM * PP)
                              : (g_sims + (size_t)(bm - 2) * BM * PP);
    int g = lane >> 2, tg = lane & 3;
#pragma unroll
    for (int mt = 0; mt < 2; mt++) {
        int m0 = wm * 32 + mt * 16 + g;
#pragma unroll
        for (int nt = 0; nt < 8; nt++) {
            int n = bn * BN + wn * 64 + nt * 8 + tg * 2;
            *(float2*)(outBase + (size_t)m0 * PP + n) =
                make_float2(acc[mt][nt][0], acc[mt][nt][1]);
            *(float2*)(outBase + (size_t)(m0 + 8) * PP + n) =
                make_float2(acc[mt][nt][2], acc[mt][nt][3]);
        }
    }
}

// ---------------- radix top-K helpers ----------------
__device__ __forceinline__ unsigned f2key(float v) {
    unsigned u = __float_as_uint(v);
    return (u & 0x80000000u) ? ~u : (u | 0x80000000u);
}
__device__ __forceinline__ float key2f(unsigned u) {
    unsigned b = (u & 0x80000000u) ? (u ^ 0x80000000u) : ~u;
    return __uint_as_float(b);
}
__device__ __forceinline__ void hist_add(unsigned* hist, unsigned d) {
    unsigned am = __activemask();
    unsigned mm = __match_any_sync(am, d);
    int leader = __ffs(mm) - 1;
    if ((int)(threadIdx.x & 31) == leader) atomicAdd(&hist[d], (unsigned)__popc(mm));
}
// Warp-shuffle suffix scan over 256-bin hist. sh[0]=digit, sh[1]=new rem, sh[2]=count >= digit.
__device__ __forceinline__ void select_digit(unsigned* hist, unsigned* aux,
                                             unsigned* sh, int rem) {
    const int t = threadIdx.x, l = t & 31, w = t >> 5;
    unsigned v = hist[t];
    unsigned s = v;
#pragma unroll
    for (int off = 1; off < 32; off <<= 1) {
        unsigned o = __shfl_down_sync(0xffffffffu, s, off);
        if (l + off < 32) s += o;
    }
    if (l == 0) aux[w] = s;
    __syncthreads();
    if (t < 8) { unsigned a = 0; for (int j = t; j < 8; j++) a += aux[j]; aux[8 + t] = a; }
    __syncthreads();
    unsigned tail = (w < 7) ? aux[8 + w + 1] : 0;
    unsigned sfx_t = s + tail;
    unsigned sfx_nx = sfx_t - v;
    if (sfx_t >= (unsigned)rem && sfx_nx < (unsigned)rem) {
        sh[0] = (unsigned)t;
        sh[1] = (unsigned)rem - sfx_nx;
        sh[2] = sfx_t;
    }
    __syncthreads();
}

#define SCAP 1024

// ---------------- merged loss kernel (512 blocks: 0-255 off, 256-511 on) ----------------
__global__ __launch_bounds__(256) void loss_kernel(const int* __restrict__ targets,
                                                   const int* __restrict__ apl) {
    __shared__ unsigned keys[PP];        // 32 KB
    __shared__ unsigned skey[SCAP];      // 4 KB
    __shared__ int      sidx[SCAP];      // 4 KB
    __shared__ unsigned hist[256];
    __shared__ unsigned aux[16];
    __shared__ float    fval[BGKNN + NPP];
    __shared__ int      idxl[BGKNN];
    __shared__ int      boost[KPOS];
    __shared__ unsigned ck[256];
    __shared__ int      ci[256];
    __shared__ unsigned sh[8];

    const int bx = blockIdx.x;
    const int mode = bx >> 8;            // 0 = offline, 1 = online
    const int row = bx & 255;
    const int t = threadIdx.x;
    const int pt = apl[targets[row]];

    if (mode == 0) {
        const float* src = g_score + (size_t)row * PP;
        const int p0 = (pt / NPP) * NPP;
        for (int p = t; p < PP; p += 256) {
            unsigned u = f2key(src[p]);
            keys[p] = ((unsigned)(p - p0) < 8u) ? 0u : u;     // mask positives
        }
        __syncthreads();
    } else {
        const float* ssrc = g_sims + (size_t)row * PP;
        unsigned bk = 0; int bi = 0x7fffffff;
        for (int p = t; p < PP; p += 256) {
            unsigned u = f2key(ssrc[p]);
            keys[p] = u;
            if (u > bk) { bk = u; bi = p >> 3; }              // cam = p & 7 == t & 7
        }
        ck[t] = bk; ci[t] = bi;
        __syncthreads();
        for (int s = 128; s >= 8; s >>= 1) {
            if (t < s) {
                unsigned ok = ck[t + s]; int oi = ci[t + s];
                if (ok > ck[t] || (ok == ck[t] && oi < ci[t])) { ck[t] = ok; ci[t] = oi; }
            }
            __syncthreads();
        }
        if (t == 0) {
            bool used[NCAMS] = {};
            for (int j = 0; j < KPOS; j++) {
                int bc = -1; unsigned bv = 0;
                for (int c = 0; c < NCAMS; c++)
                    if (!used[c] && (bc < 0 || ck[c] > bv)) { bc = c; bv = ck[c]; }
                used[bc] = true;
                int proxy = ci[bc] * NCAMS + bc;
                boost[j] = proxy;
                keys[proxy] = 0u;        // exclude from background top-40
            }
        }
        __syncthreads();
    }

    // ---- pass 1: 256-bin histogram on top byte ----
    hist[t] = 0;
    if (t == 0) sh[3] = 0;
    __syncthreads();
    for (int p = t; p < PP; p += 256) hist_add(hist, keys[p] >> 24);
    __syncthreads();
    int rem = BGKNN;
    select_digit(hist, aux, sh, rem);
    unsigned d1 = sh[0];
    rem = (int)sh[1];
    const unsigned cntGe = sh[2];
    unsigned prefix = d1 << 24;

    // ---- compact survivors (top byte >= d1) ----
    const bool useC = (cntGe <= SCAP);
    int scnt;
    if (useC) {
        for (int p = t; p < PP; p += 256) {
            unsigned u = keys[p];
            if ((u >> 24) >= d1) {
                unsigned pos = atomicAdd(&sh[3], 1u);
                skey[pos] = u; sidx[pos] = p;
            }
        }
        scnt = (int)cntGe;
    } else {
        scnt = PP;
    }
    __syncthreads();

    // ---- passes 2-4 over survivors ----
    for (int pass = 1; pass < 4; pass++) {
        const int shift = 24 - 8 * pass;
        const unsigned mask = 0xFFFFFFFFu << (shift + 8);
        hist[t] = 0;
        __syncthreads();
        for (int i = t; i < scnt; i += 256) {
            unsigned u = useC ? skey[i] : keys[i];
            if ((u & mask) == prefix) hist_add(hist, (u >> shift) & 255u);
        }
        __syncthreads();
        select_digit(hist, aux, sh, rem);
        prefix |= sh[0] << shift;
        rem = (int)sh[1];
        __syncthreads();
    }
    const unsigned T = prefix;
    const int need = rem;
    if (t == 0) { sh[4] = 0; sh[5] = 0; }
    __syncthreads();

    // ---- collect top-40 ----
    for (int i = t; i < scnt; i += 256) {
        unsigned u = useC ? skey[i] : keys[i];
        int idx = useC ? sidx[i] : i;
        if (u > T) {
            unsigned s2 = atomicAdd(&sh[5], 1u);
            if (mode == 0) fval[s2] = key2f(u); else idxl[s2] = idx;
        } else if (u == T) {
            unsigned e = atomicAdd(&sh[4], 1u);
            if (e < (unsigned)need) {
                unsigned s2 = atomicAdd(&sh[5], 1u);
                if (mode == 0) fval[s2] = key2f(u); else idxl[s2] = idx;
            }
        }
    }
    __syncthreads();

    // ---- gather values + positives ----
    if (mode == 0) {
        if (t < NPP) {
            const float* src = g_score + (size_t)row * PP;
            fval[BGKNN + t] = src[(pt / NPP) * NPP + t];
        }
    } else {
        const float* inp = g_score + (size_t)row * PP;   // values come from inputs!
        if (t < BGKNN) fval[t] = inp[idxl[t]];
        else if (t < BGKNN + KPOS) fval[t] = inp[boost[t - BGKNN]];
    }
    __syncthreads();

    // ---- log-sum-exp loss by warp 0 ----
    if (t < 32) {
        const int K = mode ? (BGKNN + KPOS) : (BGKNN + NPP);
        const int pcnt = mode ? KPOS : NPP;
        float a = (t < K) ? fval[t] * 10.0f : -1e30f;
        float b = (t + 32 < K) ? fval[t + 32] * 10.0f : -1e30f;
        float m = fmaxf(a, b);
#pragma unroll
        for (int o = 16; o; o >>= 1) m = fmaxf(m, __shfl_xor_sync(0xffffffffu, m, o));
        float e = 0.f, ps = 0.f;
        if (t < K) e += __expf(a - m);
        if (t + 32 < K) e += __expf(b - m);
        if (t + 32 >= BGKNN && t + 32 < BGKNN + pcnt) ps = b;
#pragma unroll
        for (int o = 16; o; o >>= 1) {
            e += __shfl_xor_sync(0xffffffffu, e, o);
            ps += __shfl_xor_sync(0xffffffffu, ps, o);
        }
        if (t == 0) {
            float L = m + logf(e) - ps / (float)pcnt;
            if (mode) g_Lon[row] = L; else g_Loff[row] = L;
        }
    }
}

// ---------------- deterministic parallel finalize ----------------
__global__ void finalize_kernel(const int* __restrict__ targets,
                                const int* __restrict__ apl, float* out) {
    __shared__ float lo[BB], ln[BB];
    __shared__ int cm[BB];
    __shared__ float acc[NCAMS];
    int t = threadIdx.x;
    lo[t] = g_Loff[t]; ln[t] = g_Lon[t];
    cm[t] = apl[targets[t]] % NCAMS;
    __syncthreads();
    if (t < NCAMS) {
        float so = 0.f, sn = 0.f; int n = 0;
        for (int i = 0; i < BB; i++)
            if (cm[i] == t) { so += lo[i]; sn += ln[i]; n++; }
        acc[t] = (n > 0) ? (so / n + sn / n) : 0.f;
    }
    __syncthreads();
    if (t == 0) {
        float L = 0.f;
        for (int c = 0; c < NCAMS; c++) L += acc[c];
        out[0] = L;
    }
}

// ---------------- launch ----------------
extern "C" void kernel_launch(void* const* d_in, const int* in_sizes, int n_in,
                              void* d_out, int out_size) {
    const float* features = (const float*)d_in[0];
    const float* gmemory  = (const float*)d_in[1];
    const int*   targets  = (const int*)d_in[2];
    const int*   apl      = (const int*)d_in[3];
    float* out = (float*)d_out;

    conv_kernel<<<(NBCHUNK + NACHUNK) / 256, 256>>>(gmemory, features, targets, apl);

    cudaFuncSetAttribute(gemm_kernel, cudaFuncAttributeMaxDynamicSharedMemorySize,
                         GEMM_SMEM);
    // Explicitly request max L1/smem carveout so two 96KB CTAs can co-reside per SM.
    cudaFuncSetAttribute(gemm_kernel, cudaFuncAttributePreferredSharedMemoryCarveout, 100);
    gemm_kernel<<<dim3(PP / BN, MTOT / BM), 256, GEMM_SMEM>>>();

    loss_kernel<<<2 * BB, 256>>>(targets, apl);
    finalize_kernel<<<1, 256>>>(targets, apl, out);
}